// round 4
// baseline (speedup 1.0000x reference)
#include <cuda_runtime.h>
#include <cstdint>

// ---------------- problem constants ----------------
#define NN   50000
#define NE   800000
#define INC  512
#define HID  512
#define OUTC 256

// ---------------- device scratch (no allocations allowed) ----------------
__device__ float g_h[(size_t)NN * HID];     // GEMM output h = A @ W
__device__ float g_act[(size_t)NN * HID];   // layer activation (input to next GEMM)
__device__ float g_dinv[NN];                // deg^{-1/2}
__device__ int   g_cnt[NN];                 // in-degree counts (edges only)
__device__ int   g_rowptr[NN + 1];          // CSR row pointers (by dst)
__device__ int   g_cursor[NN];              // scatter cursors
__device__ int   g_csr_src[NE];             // CSR column (src node)
__device__ float g_csr_w[NE];               // precomputed dinv[src]*dinv[dst]

// ---------------- small helpers ----------------
__device__ __forceinline__ float gelu_tanh(float x) {
    // jax.nn.gelu default: approximate=True (tanh form)
    float x3 = x * x * x;
    return 0.5f * x * (1.0f + tanhf(0.7978845608028654f * (x + 0.044715f * x3)));
}

// ---------------- prep kernels ----------------
__global__ void k_zero_cnt() {
    int i = blockIdx.x * blockDim.x + threadIdx.x;
    if (i < NN) g_cnt[i] = 0;
}

__global__ void k_count(const int* __restrict__ dst) {
    int e = blockIdx.x * blockDim.x + threadIdx.x;
    if (e < NE) atomicAdd(&g_cnt[dst[e]], 1);
}

__global__ void k_dinv() {
    int i = blockIdx.x * blockDim.x + threadIdx.x;
    if (i < NN) g_dinv[i] = rsqrtf((float)g_cnt[i] + 1.0f);
}

// single-block exclusive scan over g_cnt -> g_rowptr, also fills g_cursor
__global__ void k_scan() {
    __shared__ int s[1024];
    __shared__ int carry;
    int tid = threadIdx.x;
    if (tid == 0) { carry = 0; g_rowptr[0] = 0; }
    __syncthreads();
    for (int base = 0; base < NN; base += 1024) {
        int i = base + tid;
        int v = (i < NN) ? g_cnt[i] : 0;
        s[tid] = v;
        __syncthreads();
        #pragma unroll
        for (int off = 1; off < 1024; off <<= 1) {
            int t = (tid >= off) ? s[tid - off] : 0;
            __syncthreads();
            s[tid] += t;
            __syncthreads();
        }
        if (i < NN) {
            int incl = carry + s[tid];
            g_rowptr[i + 1] = incl;
            g_cursor[i] = incl - v;   // exclusive = start position
        }
        __syncthreads();
        if (tid == 0) carry += s[1023];
        __syncthreads();
    }
}

__global__ void k_build(const int* __restrict__ src, const int* __restrict__ dst) {
    int e = blockIdx.x * blockDim.x + threadIdx.x;
    if (e < NE) {
        int sN = src[e];
        int dN = dst[e];
        int pos = atomicAdd(&g_cursor[dN], 1);
        g_csr_src[pos] = sN;
        g_csr_w[pos] = g_dinv[sN] * g_dinv[dN];
    }
}

// ---------------- SGEMM: C[M,N] = A[M,K] @ B[K,N], fp32, FFMA2 packed ----------------
// BM=128 BN=128 BK=16, 256 threads, each thread 8x8 micro-tile (acc as 8x4 f32x2 pairs)
template <bool FROM_X>
__global__ void __launch_bounds__(256)
k_sgemm(const float* __restrict__ Xin, const float* __restrict__ B,
        int M, int Nn, int K) {
    const float* __restrict__ A = FROM_X ? Xin : g_act;

    __shared__ __align__(16) float As[16][128];   // transposed: As[k][m]
    __shared__ __align__(16) float Bs[16][128];

    int m0 = blockIdx.y * 128;
    int n0 = blockIdx.x * 128;
    int tid = threadIdx.x;
    int ty = tid >> 4;       // 0..15
    int tx = tid & 15;       // 0..15

    unsigned long long acc[8][4];
    #pragma unroll
    for (int i = 0; i < 8; i++)
        #pragma unroll
        for (int j = 0; j < 4; j++) acc[i][j] = 0ULL;

    for (int k0 = 0; k0 < K; k0 += 16) {
        // load A tile: 128 rows x 16 cols = 512 float4 slots
        #pragma unroll
        for (int jj = 0; jj < 2; jj++) {
            int slot = tid + jj * 256;
            int ar = slot >> 2;            // 0..127
            int ac = (slot & 3) * 4;       // 0,4,8,12
            int gm = m0 + ar;
            float4 v = make_float4(0.f, 0.f, 0.f, 0.f);
            if (gm < M) v = *(const float4*)&A[(size_t)gm * K + k0 + ac];
            As[ac + 0][ar] = v.x;
            As[ac + 1][ar] = v.y;
            As[ac + 2][ar] = v.z;
            As[ac + 3][ar] = v.w;
        }
        // load B tile: 16 rows x 128 cols = 512 float4 slots
        #pragma unroll
        for (int jj = 0; jj < 2; jj++) {
            int slot = tid + jj * 256;
            int br = slot >> 5;            // 0..15
            int bc = (slot & 31) * 4;      // 0..124
            *(float4*)&Bs[br][bc] = *(const float4*)&B[(size_t)(k0 + br) * Nn + n0 + bc];
        }
        __syncthreads();

        #pragma unroll
        for (int kk = 0; kk < 16; kk++) {
            float av[8];
            *(float4*)&av[0] = *(const float4*)&As[kk][ty * 8];
            *(float4*)&av[4] = *(const float4*)&As[kk][ty * 8 + 4];
            unsigned long long bp[4];
            {
                ulonglong2 q0 = *(const ulonglong2*)&Bs[kk][tx * 8];
                ulonglong2 q1 = *(const ulonglong2*)&Bs[kk][tx * 8 + 4];
                bp[0] = q0.x; bp[1] = q0.y; bp[2] = q1.x; bp[3] = q1.y;
            }
            #pragma unroll
            for (int i = 0; i < 8; i++) {
                unsigned long long ap;
                unsigned int ar = __float_as_uint(av[i]);
                asm("mov.b64 %0, {%1, %1};" : "=l"(ap) : "r"(ar));
                #pragma unroll
                for (int j = 0; j < 4; j++) {
                    asm("fma.rn.f32x2 %0, %1, %2, %0;"
                        : "+l"(acc[i][j]) : "l"(ap), "l"(bp[j]));
                }
            }
        }
        __syncthreads();
    }

    // store to g_h
    #pragma unroll
    for (int i = 0; i < 8; i++) {
        int gm = m0 + ty * 8 + i;
        if (gm < M) {
            float o[8];
            #pragma unroll
            for (int j = 0; j < 4; j++) {
                unsigned int lo, hi;
                asm("mov.b64 {%0, %1}, %2;" : "=r"(lo), "=r"(hi) : "l"(acc[i][j]));
                o[2 * j]     = __uint_as_float(lo);
                o[2 * j + 1] = __uint_as_float(hi);
            }
            float* dstp = &g_h[(size_t)gm * Nn + n0 + tx * 8];
            *(float4*)&dstp[0] = *(float4*)&o[0];
            *(float4*)&dstp[4] = *(float4*)&o[4];
        }
    }
}

// ---------------- aggregation: one warp per node, no atomics ----------------
// out[i] = agg + h[i]*dinv[i]^2 + bias  (optional tanh-GELU)
template <int C, bool DOGELU, bool TO_EXT>
__global__ void __launch_bounds__(256)
k_agg(const float* __restrict__ bias, float* __restrict__ ext_out) {
    int warp = (blockIdx.x * blockDim.x + threadIdx.x) >> 5;
    int lane = threadIdx.x & 31;
    if (warp >= NN) return;

    constexpr int V = C / 128;      // float4 per lane: 4 (C=512) or 2 (C=256)
    float4 acc[V];

    const float4* hrow = (const float4*)&g_h[(size_t)warp * C];
    float ws = g_dinv[warp];
    ws *= ws;
    #pragma unroll
    for (int j = 0; j < V; j++) {
        float4 v = hrow[j * 32 + lane];
        acc[j] = make_float4(v.x * ws, v.y * ws, v.z * ws, v.w * ws);
    }

    int e0 = g_rowptr[warp];
    int e1 = g_rowptr[warp + 1];
    for (int e = e0; e < e1; e++) {
        int s = g_csr_src[e];          // uniform across warp -> broadcast
        float w = g_csr_w[e];
        const float4* hs = (const float4*)&g_h[(size_t)s * C];
        #pragma unroll
        for (int j = 0; j < V; j++) {
            float4 v = hs[j * 32 + lane];
            acc[j].x += v.x * w;
            acc[j].y += v.y * w;
            acc[j].z += v.z * w;
            acc[j].w += v.w * w;
        }
    }

    const float4* bv = (const float4*)bias;
    float4* ov = TO_EXT ? (float4*)&ext_out[(size_t)warp * C]
                        : (float4*)&g_act[(size_t)warp * C];
    #pragma unroll
    for (int j = 0; j < V; j++) {
        float4 bb = bv[j * 32 + lane];
        float4 r;
        r.x = acc[j].x + bb.x;
        r.y = acc[j].y + bb.y;
        r.z = acc[j].z + bb.z;
        r.w = acc[j].w + bb.w;
        if (DOGELU) {
            r.x = gelu_tanh(r.x);
            r.y = gelu_tanh(r.y);
            r.z = gelu_tanh(r.z);
            r.w = gelu_tanh(r.w);
        }
        ov[j * 32 + lane] = r;
    }
}

// ---------------- launch ----------------
extern "C" void kernel_launch(void* const* d_in, const int* in_sizes, int n_in,
                              void* d_out, int out_size) {
    const float* x   = (const float*)d_in[0];
    const int*   ei  = (const int*)d_in[1];
    const float* W1  = (const float*)d_in[2];
    const float* b1  = (const float*)d_in[3];
    const float* W2  = (const float*)d_in[4];
    const float* b2  = (const float*)d_in[5];
    const float* W3  = (const float*)d_in[6];
    const float* b3  = (const float*)d_in[7];
    float* out = (float*)d_out;

    const int* src = ei;
    const int* dst = ei + NE;

    // ---- graph preprocessing (every call; deterministic CSR order via cursors) ----
    k_zero_cnt<<<(NN + 255) / 256, 256>>>();
    k_count<<<(NE + 255) / 256, 256>>>(dst);
    k_dinv<<<(NN + 255) / 256, 256>>>();
    k_scan<<<1, 1024>>>();
    k_build<<<(NE + 255) / 256, 256>>>(src, dst);

    dim3 g512(HID / 128, (NN + 127) / 128);   // (4, 391)
    dim3 g256(OUTC / 128, (NN + 127) / 128);  // (2, 391)
    int aggBlocks = (NN * 32 + 255) / 256;    // one warp per node

    // ---- layer 1: h = x @ W1 ; act = gelu(agg + h*dinv^2 + b1) ----
    k_sgemm<true><<<g512, 256>>>(x, W1, NN, HID, INC);
    k_agg<HID, true, false><<<aggBlocks, 256>>>(b1, nullptr);

    // ---- layer 2 ----
    k_sgemm<false><<<g512, 256>>>(nullptr, W2, NN, HID, HID);
    k_agg<HID, true, false><<<aggBlocks, 256>>>(b2, nullptr);

    // ---- layer 3 (no gelu, writes d_out) ----
    k_sgemm<false><<<g256, 256>>>(nullptr, W3, NN, OUTC, HID);
    k_agg<OUTC, false, true><<<aggBlocks, 256>>>(b3, out);
}

// round 10
// speedup vs baseline: 1.8228x; 1.8228x over previous
#include <cuda_runtime.h>
#include <cuda_bf16.h>
#include <cstdint>

// ---------------- problem constants ----------------
#define NN   50000
#define NE   800000
#define INC  512
#define HID  512
#define OUTC 256
#define KDIM 512

// ---------------- device scratch ----------------
__device__ float g_h[(size_t)NN * HID];     // GEMM output
__device__ float g_act[(size_t)NN * HID];   // layer activation
__device__ float g_dinv[NN];
__device__ int   g_cnt[NN];
__device__ int   g_rowptr[NN + 1];
__device__ int   g_cursor[NN];
__device__ int   g_csr_src[NE];
__device__ float g_csr_w[NE];

// transposed + bf16-split weights: WT[Nn][K]
#define W1T_OFF 0
#define W2T_OFF (512 * 512)
#define W3T_OFF (2 * 512 * 512)
#define WT_TOT  (2 * 512 * 512 + 256 * 512)
__device__ __nv_bfloat16 g_whT[WT_TOT];
__device__ __nv_bfloat16 g_wlT[WT_TOT];

// ---------------- helpers ----------------
__device__ __forceinline__ float gelu_tanh(float x) {
    float x3 = x * x * x;
    return 0.5f * x * (1.0f + tanhf(0.7978845608028654f * (x + 0.044715f * x3)));
}

__device__ __forceinline__ uint32_t s2u(const void* p) {
    uint32_t a;
    asm("{ .reg .u64 t; cvta.to.shared.u64 t, %1; cvt.u32.u64 %0, t; }"
        : "=r"(a) : "l"(p));
    return a;
}

// split fp32x4 into hi/lo bf16 (4 bf16 packed as uint2)
__device__ __forceinline__ void split4(float4 v, uint2& hi, uint2& lo) {
    __nv_bfloat16 h0 = __float2bfloat16(v.x);
    __nv_bfloat16 h1 = __float2bfloat16(v.y);
    __nv_bfloat16 h2 = __float2bfloat16(v.z);
    __nv_bfloat16 h3 = __float2bfloat16(v.w);
    __nv_bfloat16 l0 = __float2bfloat16(v.x - __bfloat162float(h0));
    __nv_bfloat16 l1 = __float2bfloat16(v.y - __bfloat162float(h1));
    __nv_bfloat16 l2 = __float2bfloat16(v.z - __bfloat162float(h2));
    __nv_bfloat16 l3 = __float2bfloat16(v.w - __bfloat162float(h3));
    __nv_bfloat162 a; a.x = h0; a.y = h1;
    __nv_bfloat162 b; b.x = h2; b.y = h3;
    __nv_bfloat162 c; c.x = l0; c.y = l1;
    __nv_bfloat162 d; d.x = l2; d.y = l3;
    hi.x = *(uint32_t*)&a; hi.y = *(uint32_t*)&b;
    lo.x = *(uint32_t*)&c; lo.y = *(uint32_t*)&d;
}

__device__ __forceinline__ void ldm_x4(uint32_t* r, uint32_t addr) {
    asm volatile("ldmatrix.sync.aligned.m8n8.x4.shared.b16 {%0,%1,%2,%3}, [%4];"
                 : "=r"(r[0]), "=r"(r[1]), "=r"(r[2]), "=r"(r[3]) : "r"(addr));
}
__device__ __forceinline__ void ldm_x2(uint32_t* r, uint32_t addr) {
    asm volatile("ldmatrix.sync.aligned.m8n8.x2.shared.b16 {%0,%1}, [%2];"
                 : "=r"(r[0]), "=r"(r[1]) : "r"(addr));
}
__device__ __forceinline__ void mma16816(float* d, const uint32_t* a, const uint32_t* b) {
    asm volatile(
        "mma.sync.aligned.m16n8k16.row.col.f32.bf16.bf16.f32 "
        "{%0,%1,%2,%3}, {%4,%5,%6,%7}, {%8,%9}, {%0,%1,%2,%3};"
        : "+f"(d[0]), "+f"(d[1]), "+f"(d[2]), "+f"(d[3])
        : "r"(a[0]), "r"(a[1]), "r"(a[2]), "r"(a[3]), "r"(b[0]), "r"(b[1]));
}

// ---------------- prep kernels ----------------
__global__ void k_zero_cnt() {
    int i = blockIdx.x * blockDim.x + threadIdx.x;
    if (i < NN) g_cnt[i] = 0;
}

__global__ void k_count(const int* __restrict__ dst) {
    int e = blockIdx.x * blockDim.x + threadIdx.x;
    if (e < NE) atomicAdd(&g_cnt[dst[e]], 1);
}

__global__ void k_dinv() {
    int i = blockIdx.x * blockDim.x + threadIdx.x;
    if (i < NN) g_dinv[i] = rsqrtf((float)g_cnt[i] + 1.0f);
}

// fast single-block scan: serial-per-thread + shuffle block scan
__global__ void k_scan() {
    constexpr int CH = (NN + 1023) / 1024;   // 49
    __shared__ int wsum[32];
    int tid = threadIdx.x;
    int lane = tid & 31, wid = tid >> 5;
    int base = tid * CH;

    int s = 0;
    for (int i = 0; i < CH; i++) {
        int idx = base + i;
        if (idx < NN) s += g_cnt[idx];
    }
    int scan = s;
    #pragma unroll
    for (int o = 1; o < 32; o <<= 1) {
        int t = __shfl_up_sync(~0u, scan, o);
        if (lane >= o) scan += t;
    }
    if (lane == 31) wsum[wid] = scan;
    __syncthreads();
    if (wid == 0) {
        int t = wsum[lane];
        int sc = t;
        #pragma unroll
        for (int o = 1; o < 32; o <<= 1) {
            int u = __shfl_up_sync(~0u, sc, o);
            if (lane >= o) sc += u;
        }
        wsum[lane] = sc - t;
    }
    __syncthreads();
    int run = wsum[wid] + (scan - s);
    for (int i = 0; i < CH; i++) {
        int idx = base + i;
        if (idx < NN) {
            int t = g_cnt[idx];
            g_cursor[idx] = run;
            run += t;
            g_rowptr[idx + 1] = run;
        }
    }
    if (tid == 0) g_rowptr[0] = 0;
}

__global__ void k_build(const int* __restrict__ src, const int* __restrict__ dst) {
    int e = blockIdx.x * blockDim.x + threadIdx.x;
    if (e < NE) {
        int sN = src[e];
        int dN = dst[e];
        int pos = atomicAdd(&g_cursor[dN], 1);
        g_csr_src[pos] = sN;
        g_csr_w[pos] = g_dinv[sN] * g_dinv[dN];
    }
}

// transpose W[K,Nn] -> WT[Nn,K] with bf16 hi/lo split
__global__ void k_wprep(const float* __restrict__ W, int K, int Nn, int woff) {
    __shared__ float t[32][33];
    int n0 = blockIdx.x * 32, k0 = blockIdx.y * 32;
    int tx = threadIdx.x, ty = threadIdx.y;   // 32 x 8
    #pragma unroll
    for (int i = 0; i < 4; i++)
        t[ty + 8 * i][tx] = W[(size_t)(k0 + ty + 8 * i) * Nn + n0 + tx];
    __syncthreads();
    #pragma unroll
    for (int i = 0; i < 4; i++) {
        int n = n0 + ty + 8 * i;
        int k = k0 + tx;
        float v = t[tx][ty + 8 * i];
        __nv_bfloat16 h = __float2bfloat16(v);
        g_whT[woff + (size_t)n * K + k] = h;
        g_wlT[woff + (size_t)n * K + k] = __float2bfloat16(v - __bfloat162float(h));
    }
}

// ---------------- bf16-split mma.sync GEMM ----------------
// C[M,Nn] = A[M,512] @ WT^T ; block 128x128, BK=32, 8 warps (2x4), warp tile 64x32
#define SLD 40   // smem row stride (bf16 elems): 80B, 16B-aligned rows, ldmatrix conflict-free

template <bool FROM_X>
__device__ __forceinline__ void gemm_load_regs(
    const float* __restrict__ A, const __nv_bfloat16* __restrict__ whT,
    const __nv_bfloat16* __restrict__ wlT, int M, int m0, int n0,
    int tid, int kc, float4* pa, uint4* pbh, uint4* pbl) {
    int k0 = kc * 32;
    #pragma unroll
    for (int j = 0; j < 4; j++) {
        int slot = tid + j * 256;
        int r = slot >> 3;          // 0..127
        int q = slot & 7;           // float4 idx
        int gm = m0 + r;
        pa[j] = (gm < M) ? *(const float4*)&A[(size_t)gm * KDIM + k0 + q * 4]
                         : make_float4(0.f, 0.f, 0.f, 0.f);
    }
    #pragma unroll
    for (int j = 0; j < 2; j++) {
        int slot = tid + j * 256;
        int r = slot >> 2;          // 0..127 (n row)
        int q = slot & 3;           // uint4 (8 bf16)
        size_t off = (size_t)(n0 + r) * KDIM + k0 + q * 8;
        pbh[j] = *(const uint4*)&whT[off];
        pbl[j] = *(const uint4*)&wlT[off];
    }
}

__device__ __forceinline__ void gemm_store_smem(
    __nv_bfloat16* As_hi, __nv_bfloat16* As_lo,
    __nv_bfloat16* Bs_hi, __nv_bfloat16* Bs_lo,
    int tid, const float4* pa, const uint4* pbh, const uint4* pbl) {
    #pragma unroll
    for (int j = 0; j < 4; j++) {
        int slot = tid + j * 256;
        int r = slot >> 3;
        int q = slot & 7;
        uint2 hi, lo;
        split4(pa[j], hi, lo);
        *(uint2*)&As_hi[r * SLD + q * 4] = hi;
        *(uint2*)&As_lo[r * SLD + q * 4] = lo;
    }
    #pragma unroll
    for (int j = 0; j < 2; j++) {
        int slot = tid + j * 256;
        int r = slot >> 2;
        int q = slot & 3;
        *(uint4*)&Bs_hi[r * SLD + q * 8] = pbh[j];
        *(uint4*)&Bs_lo[r * SLD + q * 8] = pbl[j];
    }
}

template <bool FROM_X>
__global__ void __launch_bounds__(256, 1)
k_mmagemm(const float* __restrict__ Xin, int M, int Nn, int woff) {
    __shared__ __align__(16) __nv_bfloat16 As_hi[128 * SLD];
    __shared__ __align__(16) __nv_bfloat16 As_lo[128 * SLD];
    __shared__ __align__(16) __nv_bfloat16 Bs_hi[128 * SLD];
    __shared__ __align__(16) __nv_bfloat16 Bs_lo[128 * SLD];

    const float* __restrict__ A = FROM_X ? Xin : g_act;
    const __nv_bfloat16* __restrict__ whT = g_whT + woff;
    const __nv_bfloat16* __restrict__ wlT = g_wlT + woff;

    int tid = threadIdx.x;
    int wid = tid >> 5;
    int lane = tid & 31;
    int wm = wid >> 2;        // 0..1
    int wn = wid & 3;         // 0..3
    int m0 = blockIdx.y * 128;
    int n0 = blockIdx.x * 128;

    uint32_t ah_base = s2u(As_hi);
    uint32_t al_base = s2u(As_lo);
    uint32_t bh_base = s2u(Bs_hi);
    uint32_t bl_base = s2u(Bs_lo);

    float acc[4][4][4];
    #pragma unroll
    for (int i = 0; i < 4; i++)
        #pragma unroll
        for (int j = 0; j < 4; j++)
            #pragma unroll
            for (int q = 0; q < 4; q++) acc[i][j][q] = 0.f;

    float4 pa[4];
    uint4 pbh[2], pbl[2];

    gemm_load_regs<FROM_X>(A, whT, wlT, M, m0, n0, tid, 0, pa, pbh, pbl);

    for (int kc = 0; kc < 16; kc++) {
        gemm_store_smem(As_hi, As_lo, Bs_hi, Bs_lo, tid, pa, pbh, pbl);
        __syncthreads();
        if (kc < 15)
            gemm_load_regs<FROM_X>(A, whT, wlT, M, m0, n0, tid, kc + 1, pa, pbh, pbl);

        #pragma unroll
        for (int kk = 0; kk < 32; kk += 16) {
            // A fragments: 4 m-tiles, hi/lo
            uint32_t fah[4][4], fal[4][4];
            int arow = wm * 64 + (lane & 15);
            int acol = kk + (lane >> 4) * 8;
            #pragma unroll
            for (int mt = 0; mt < 4; mt++) {
                uint32_t ao = (uint32_t)((arow + mt * 16) * SLD + acol) * 2;
                ldm_x4(fah[mt], ah_base + ao);
                ldm_x4(fal[mt], al_base + ao);
            }
            // B fragments: 4 n-tiles, hi/lo
            uint32_t fbh[4][2], fbl[4][2];
            int brow = wn * 32 + (lane & 7);
            int bcol = kk + ((lane >> 3) & 1) * 8;
            #pragma unroll
            for (int nt = 0; nt < 4; nt++) {
                uint32_t bo = (uint32_t)((brow + nt * 8) * SLD + bcol) * 2;
                ldm_x2(fbh[nt], bh_base + bo);
                ldm_x2(fbl[nt], bl_base + bo);
            }
            #pragma unroll
            for (int mt = 0; mt < 4; mt++)
                #pragma unroll
                for (int nt = 0; nt < 4; nt++) {
                    mma16816(acc[mt][nt], fah[mt], fbh[nt]);
                    mma16816(acc[mt][nt], fah[mt], fbl[nt]);
                    mma16816(acc[mt][nt], fal[mt], fbh[nt]);
                }
        }
        __syncthreads();
    }

    // epilogue: c0,c1 -> (row g, col t*2..t*2+1); c2,c3 -> row g+8
    int g = lane >> 2;
    int t = lane & 3;
    #pragma unroll
    for (int mt = 0; mt < 4; mt++) {
        int row0 = m0 + wm * 64 + mt * 16 + g;
        #pragma unroll
        for (int nt = 0; nt < 4; nt++) {
            int col = n0 + wn * 32 + nt * 8 + t * 2;
            if (row0 < M) {
                float2 v0 = make_float2(acc[mt][nt][0], acc[mt][nt][1]);
                *(float2*)&g_h[(size_t)row0 * Nn + col] = v0;
            }
            if (row0 + 8 < M) {
                float2 v1 = make_float2(acc[mt][nt][2], acc[mt][nt][3]);
                *(float2*)&g_h[(size_t)(row0 + 8) * Nn + col] = v1;
            }
        }
    }
}

// ---------------- aggregation: one warp per node, no atomics ----------------
template <int C, bool DOGELU, bool TO_EXT>
__global__ void __launch_bounds__(256)
k_agg(const float* __restrict__ bias, float* __restrict__ ext_out) {
    int warp = (blockIdx.x * blockDim.x + threadIdx.x) >> 5;
    int lane = threadIdx.x & 31;
    if (warp >= NN) return;

    constexpr int V = C / 128;
    float4 acc[V];

    const float4* hrow = (const float4*)&g_h[(size_t)warp * C];
    float ws = g_dinv[warp];
    ws *= ws;
    #pragma unroll
    for (int j = 0; j < V; j++) {
        float4 v = hrow[j * 32 + lane];
        acc[j] = make_float4(v.x * ws, v.y * ws, v.z * ws, v.w * ws);
    }

    int e0 = g_rowptr[warp];
    int e1 = g_rowptr[warp + 1];
    for (int e = e0; e < e1; e++) {
        int s = g_csr_src[e];
        float w = g_csr_w[e];
        const float4* hs = (const float4*)&g_h[(size_t)s * C];
        #pragma unroll
        for (int j = 0; j < V; j++) {
            float4 v = hs[j * 32 + lane];
            acc[j].x += v.x * w;
            acc[j].y += v.y * w;
            acc[j].z += v.z * w;
            acc[j].w += v.w * w;
        }
    }

    const float4* bv = (const float4*)bias;
    float4* ov = TO_EXT ? (float4*)&ext_out[(size_t)warp * C]
                        : (float4*)&g_act[(size_t)warp * C];
    #pragma unroll
    for (int j = 0; j < V; j++) {
        float4 bb = bv[j * 32 + lane];
        float4 r;
        r.x = acc[j].x + bb.x;
        r.y = acc[j].y + bb.y;
        r.z = acc[j].z + bb.z;
        r.w = acc[j].w + bb.w;
        if (DOGELU) {
            r.x = gelu_tanh(r.x);
            r.y = gelu_tanh(r.y);
            r.z = gelu_tanh(r.z);
            r.w = gelu_tanh(r.w);
        }
        ov[j * 32 + lane] = r;
    }
}

// ---------------- launch ----------------
extern "C" void kernel_launch(void* const* d_in, const int* in_sizes, int n_in,
                              void* d_out, int out_size) {
    const float* x  = (const float*)d_in[0];
    const int*   ei = (const int*)d_in[1];
    const float* W1 = (const float*)d_in[2];
    const float* b1 = (const float*)d_in[3];
    const float* W2 = (const float*)d_in[4];
    const float* b2 = (const float*)d_in[5];
    const float* W3 = (const float*)d_in[6];
    const float* b3 = (const float*)d_in[7];
    float* out = (float*)d_out;

    const int* src = ei;
    const int* dst = ei + NE;

    // ---- graph preprocessing ----
    k_zero_cnt<<<(NN + 255) / 256, 256>>>();
    k_count<<<(NE + 255) / 256, 256>>>(dst);
    k_dinv<<<(NN + 255) / 256, 256>>>();
    k_scan<<<1, 1024>>>();
    k_build<<<(NE + 255) / 256, 256>>>(src, dst);

    // ---- weight transpose + bf16 split ----
    dim3 wblk(32, 8);
    k_wprep<<<dim3(512 / 32, 512 / 32), wblk>>>(W1, 512, 512, W1T_OFF);
    k_wprep<<<dim3(512 / 32, 512 / 32), wblk>>>(W2, 512, 512, W2T_OFF);
    k_wprep<<<dim3(256 / 32, 512 / 32), wblk>>>(W3, 512, 256, W3T_OFF);

    dim3 g512(HID / 128, (NN + 127) / 128);    // (4, 391)
    dim3 g256(OUTC / 128, (NN + 127) / 128);   // (2, 391)
    int aggBlocks = (NN * 32 + 255) / 256;

    // ---- layer 1 ----
    k_mmagemm<true><<<g512, 256>>>(x, NN, HID, W1T_OFF);
    k_agg<HID, true, false><<<aggBlocks, 256>>>(b1, nullptr);

    // ---- layer 2 ----
    k_mmagemm<false><<<g512, 256>>>(nullptr, NN, HID, W2T_OFF);
    k_agg<HID, true, false><<<aggBlocks, 256>>>(b2, nullptr);

    // ---- layer 3 ----
    k_mmagemm<false><<<g256, 256>>>(nullptr, NN, OUTC, W3T_OFF);
    k_agg<OUTC, false, true><<<aggBlocks, 256>>>(b3, out);
}